// round 1
// baseline (speedup 1.0000x reference)
#include <cuda_runtime.h>

// TiDHy collapses algebraically: r stays zero through the scan, so
//   sl_rhat = sum_t mean_b sum_d (b_sd[d] - X[b,t,d])^2   (all T timesteps)
//   sl_rbar = same but t >= 1
//   temp_loss = 0, r2_losses = 0, r0 = zeros(B,R), r2 = zeros(B,R2)
// One fused reduction kernel over X (8 MB), plus zero-fill of d_out.

#define NB 512
#define NT 256

static constexpr int Bc = 128;   // batch
static constexpr int Tc = 32;    // timesteps
static constexpr int Dc = 512;   // input dim
static constexpr int NE4 = Bc * Tc * Dc / 4;   // 524288 float4 elements
static constexpr int D4 = Dc / 4;              // 128 float4 per row

__device__ float2 g_partials[NB];
__device__ int    g_counter = 0;

__global__ void __launch_bounds__(NT)
tidhy_fused_kernel(const float4* __restrict__ X4,
                   const float4* __restrict__ bsd4,
                   float* __restrict__ out, int out_size)
{
    const int tid  = threadIdx.x;
    const int bid  = blockIdx.x;
    const int gtid = bid * NT + tid;
    const int gsz  = NB * NT;

    // Zero the full output (scalars 2,3 and r0/r2 blocks stay zero; out[0],out[1]
    // are overwritten by the last block below, which runs strictly after all
    // blocks have passed this point).
    for (int i = gtid; i < out_size; i += gsz)
        out[i] = 0.0f;

    // Grid-stride reduction over X as float4.
    float tot = 0.0f;   // sum over ALL (b,t,d) of (x - b_sd)^2
    float tz  = 0.0f;   // same, restricted to t == 0
    for (int i = gtid; i < NE4; i += gsz) {
        const int d4  = i & (D4 - 1);
        const int row = i >> 7;          // row = b*T + t
        float4 x = X4[i];
        float4 bs = __ldg(&bsd4[d4]);
        float dx = x.x - bs.x;
        float dy = x.y - bs.y;
        float dz = x.z - bs.z;
        float dw = x.w - bs.w;
        float s  = dx * dx + dy * dy + dz * dz + dw * dw;
        tot += s;
        if ((row & (Tc - 1)) == 0) tz += s;
    }

    __shared__ float s_tot[NT];
    __shared__ float s_tz[NT];
    __shared__ int   s_last;
    s_tot[tid] = tot;
    s_tz[tid]  = tz;
    __syncthreads();
    for (int o = NT / 2; o > 0; o >>= 1) {
        if (tid < o) {
            s_tot[tid] += s_tot[tid + o];
            s_tz[tid]  += s_tz[tid + o];
        }
        __syncthreads();
    }

    if (tid == 0) {
        g_partials[bid] = make_float2(s_tot[0], s_tz[0]);
        __threadfence();
        int old = atomicAdd(&g_counter, 1);
        s_last = (old == NB - 1) ? 1 : 0;
    }
    __syncthreads();

    if (s_last) {
        // Last block: deterministic final reduction of the NB partials.
        __threadfence();
        float ft = 0.0f, f0 = 0.0f;
        for (int i = tid; i < NB; i += NT) {
            float2 p = g_partials[i];
            ft += p.x;
            f0 += p.y;
        }
        s_tot[tid] = ft;
        s_tz[tid]  = f0;
        __syncthreads();
        for (int o = NT / 2; o > 0; o >>= 1) {
            if (tid < o) {
                s_tot[tid] += s_tot[tid + o];
                s_tz[tid]  += s_tz[tid + o];
            }
            __syncthreads();
        }
        if (tid == 0) {
            const float total = s_tot[0];
            const float tzero = s_tz[0];
            out[0] = total / (float)Bc;            // sl_rhat (all t)
            out[1] = (total - tzero) / (float)Bc;  // sl_rbar (t >= 1)
            // out[2] (temp_loss) and out[3] (r2_losses) remain 0 from zero-fill.
            g_counter = 0;   // reset for next graph replay
        }
    }
}

extern "C" void kernel_launch(void* const* d_in, const int* in_sizes, int n_in,
                              void* d_out, int out_size)
{
    // metadata order: X, rng, W_sd, b_sd, W_h1, b_h1, ln_scale, ln_bias,
    //                 W_h2, b_h2, W_h3, b_h3, temporal
    const float4* X4   = (const float4*)d_in[0];
    const float4* bsd4 = (const float4*)d_in[3];
    float* out = (float*)d_out;

    tidhy_fused_kernel<<<NB, NT>>>(X4, bsd4, out, out_size);
}

// round 4
// speedup vs baseline: 1.0036x; 1.0036x over previous
#include <cuda_runtime.h>

// TiDHy collapses algebraically: r stays zero through the scan, so
//   sl_rhat = sum_t mean_b sum_d (b_sd[d] - X[b,t,d])^2   (all T)
//   sl_rbar = same, t >= 1;  temp_loss = 0, r2_losses = 0, r0/r2 = zeros.
// One fused latency-optimized reduction over X (8 MB) + zero-fill of d_out.
//
// R2: explicit MLP=8 (front-batched independent LDG.128), uniform-t per
// thread (stride 65536 keeps d and t invariant across the 8 loads),
// warp-shuffle reductions.

#define NB 256
#define NT 256
#define U  8

static constexpr int Bc  = 128;                 // batch
static constexpr int Tc  = 32;                  // timesteps
static constexpr int Dc  = 512;                 // input dim
static constexpr int NE4 = Bc * Tc * Dc / 4;    // 524288 float4
static constexpr int GSZ = NB * NT;             // 65536 threads; GSZ*U == NE4

__device__ float2 g_partials[NB];
__device__ int    g_counter = 0;

__global__ void __launch_bounds__(NT)
tidhy_fused_kernel(const float4* __restrict__ X4,
                   const float4* __restrict__ bsd4,
                   float* __restrict__ out, int out_size)
{
    const int tid  = threadIdx.x;
    const int bid  = blockIdx.x;
    const int gtid = bid * NT + tid;

    // Zero the output tuple (out[0..1] overwritten by the last block below).
    for (int i = gtid; i < out_size; i += GSZ)
        out[i] = 0.0f;

    // Front-batched independent loads: MLP = 8.
    float4 xs[U];
    const float4* p = X4 + gtid;
#pragma unroll
    for (int u = 0; u < U; u++)
        xs[u] = p[u * GSZ];

    // Stride GSZ is a multiple of 128 (=D/4) and of 128*32 (=D/4*T), so both
    // the d-index and the timestep are invariant across the 8 loads.
    const float4 bs  = __ldg(&bsd4[gtid & 127]);
    const bool   is_t0 = (((gtid >> 7) & (Tc - 1)) == 0);

    float s = 0.0f;
#pragma unroll
    for (int u = 0; u < U; u++) {
        float dx = xs[u].x - bs.x;
        float dy = xs[u].y - bs.y;
        float dz = xs[u].z - bs.z;
        float dw = xs[u].w - bs.w;
        s += dx * dx + dy * dy + dz * dz + dw * dw;
    }
    float tz = is_t0 ? s : 0.0f;   // portion belonging to t == 0

    // Warp reduction.
#pragma unroll
    for (int o = 16; o > 0; o >>= 1) {
        s  += __shfl_xor_sync(0xFFFFFFFFu, s,  o);
        tz += __shfl_xor_sync(0xFFFFFFFFu, tz, o);
    }

    __shared__ float s_tot[NT / 32];
    __shared__ float s_tz [NT / 32];
    __shared__ int   s_last;
    const int wid = tid >> 5;
    const int lid = tid & 31;
    if (lid == 0) { s_tot[wid] = s; s_tz[wid] = tz; }
    __syncthreads();

    if (wid == 0) {
        float bt = (lid < NT / 32) ? s_tot[lid] : 0.0f;
        float bz = (lid < NT / 32) ? s_tz [lid] : 0.0f;
#pragma unroll
        for (int o = 4; o > 0; o >>= 1) {
            bt += __shfl_xor_sync(0xFFFFFFFFu, bt, o);
            bz += __shfl_xor_sync(0xFFFFFFFFu, bz, o);
        }
        if (lid == 0) {
            g_partials[bid] = make_float2(bt, bz);
            __threadfence();
            int old = atomicAdd(&g_counter, 1);
            s_last = (old == NB - 1) ? 1 : 0;
        }
    }
    __syncthreads();

    if (s_last) {
        // Last block: deterministic final reduction of NB partials.
        __threadfence();
        float ft = 0.0f, f0 = 0.0f;
        for (int i = tid; i < NB; i += NT) {
            float2 pp = g_partials[i];
            ft += pp.x;
            f0 += pp.y;
        }
#pragma unroll
        for (int o = 16; o > 0; o >>= 1) {
            ft += __shfl_xor_sync(0xFFFFFFFFu, ft, o);
            f0 += __shfl_xor_sync(0xFFFFFFFFu, f0, o);
        }
        if (lid == 0) { s_tot[wid] = ft; s_tz[wid] = f0; }
        __syncthreads();
        if (tid == 0) {
            float tot = 0.0f, tzr = 0.0f;
#pragma unroll
            for (int w = 0; w < NT / 32; w++) { tot += s_tot[w]; tzr += s_tz[w]; }
            out[0] = tot / (float)Bc;           // sl_rhat (all t)
            out[1] = (tot - tzr) / (float)Bc;   // sl_rbar (t >= 1)
            g_counter = 0;                      // reset for next graph replay
        }
    }
}

extern "C" void kernel_launch(void* const* d_in, const int* in_sizes, int n_in,
                              void* d_out, int out_size)
{
    const float4* X4   = (const float4*)d_in[0];
    const float4* bsd4 = (const float4*)d_in[3];
    float* out = (float*)d_out;

    tidhy_fused_kernel<<<NB, NT>>>(X4, bsd4, out, out_size);
}